// round 15
// baseline (speedup 1.0000x reference)
#include <cuda_runtime.h>
#include <cuda_bf16.h>
#include <cuda_fp16.h>
#include <math.h>
#include <stdint.h>

#define BB   2
#define NN   2048
#define DIM  512
#define HH   8
#define DD   64
#define BN   (BB*NN)    // 4096
#define BHD  (BB*HH)    // 16

typedef unsigned long long u64;
typedef unsigned int u32;

// fp32 scratch (qkv output; q,k consumed by LN, v by transpose)
__device__ float g_q[BHD*NN*DD];
__device__ float g_k[BHD*NN*DD];
__device__ float g_v[BHD*NN*DD];

// bf16 hi/lo scratch
__device__ __nv_bfloat16 g_xh[BN*DIM],    g_xl[BN*DIM];
__device__ __nv_bfloat16 g_winh[1536*512], g_winl[1536*512];   // [n][k]
__device__ __nv_bfloat16 g_wouth[512*512], g_woutl[512*512];   // [n][k]
__device__ __nv_bfloat16 g_qh[BHD*NN*DD], g_ql[BHD*NN*DD];
__device__ __nv_bfloat16 g_kh[BHD*NN*DD], g_kl[BHD*NN*DD];
__device__ __nv_bfloat16 g_vth[BHD*DD*NN], g_vtl[BHD*DD*NN];   // [bh][d][n]
__device__ __nv_bfloat16 g_atth[BN*DIM],  g_attl[BN*DIM];

// positional bias table: e(i,j) = wrapped squared distance, fp16 (8 MB)
__device__ __half g_eb[(size_t)NN*NN];

// ---------------------------------------------------------------------------
// helpers
// ---------------------------------------------------------------------------
__device__ __forceinline__ void mma16816(float* c,
    u32 a0, u32 a1, u32 a2, u32 a3, u32 b0, u32 b1)
{
    asm volatile(
        "mma.sync.aligned.m16n8k16.row.col.f32.bf16.bf16.f32 "
        "{%0,%1,%2,%3}, {%4,%5,%6,%7}, {%8,%9}, {%0,%1,%2,%3};"
        : "+f"(c[0]), "+f"(c[1]), "+f"(c[2]), "+f"(c[3])
        : "r"(a0), "r"(a1), "r"(a2), "r"(a3), "r"(b0), "r"(b1));
}
__device__ __forceinline__ void ldsm4(u32& r0, u32& r1, u32& r2, u32& r3, u32 addr) {
    asm volatile("ldmatrix.sync.aligned.m8n8.x4.shared.b16 {%0,%1,%2,%3}, [%4];"
        : "=r"(r0), "=r"(r1), "=r"(r2), "=r"(r3) : "r"(addr));
}
__device__ __forceinline__ float ex2f(float x) {
    float y;
    asm("ex2.approx.f32 %0, %1;" : "=f"(y) : "f"(x));
    return y;
}
__device__ __forceinline__ u32 pack_bf(__nv_bfloat16 a, __nv_bfloat16 b) {
    return (u32)__bfloat16_as_ushort(a) | ((u32)__bfloat16_as_ushort(b) << 16);
}
__device__ __forceinline__ u32 pack_hi2(float x, float y) {
    return pack_bf(__float2bfloat16(x), __float2bfloat16(y));
}
__device__ __forceinline__ u32 pack_lo2(float x, float y) {
    __nv_bfloat16 hx = __float2bfloat16(x), hy = __float2bfloat16(y);
    return pack_bf(__float2bfloat16(x - __bfloat162float(hx)),
                   __float2bfloat16(y - __bfloat162float(hy)));
}
__device__ __forceinline__ u32 smem_u32(const void* p) {
    u32 a;
    asm("{ .reg .u64 t; cvta.to.shared.u64 t, %1; cvt.u32.u64 %0, t; }"
        : "=r"(a) : "l"(p));
    return a;
}

#define GP 72
__device__ __forceinline__ u32 lane_a_off(int lane) {
    int m4 = lane >> 3, r8 = lane & 7;
    return (u32)((((m4 & 1) * 8 + r8) * GP + (m4 >> 1) * 8) * 2);
}
__device__ __forceinline__ u32 lane_b_off(int lane) {
    int m4 = lane >> 3, r8 = lane & 7;
    return (u32)((((m4 >> 1) * 8 + r8) * GP + (m4 & 1) * 8) * 2);
}

// ---------------------------------------------------------------------------
// prep kernels
// ---------------------------------------------------------------------------
__global__ void prep_x_kernel(const float* __restrict__ x) {
    int idx = blockIdx.x * 256 + threadIdx.x;
    float4 v = ((const float4*)x)[idx];
    u64 h = (u64)pack_hi2(v.x, v.y) | ((u64)pack_hi2(v.z, v.w) << 32);
    u64 l = (u64)pack_lo2(v.x, v.y) | ((u64)pack_lo2(v.z, v.w) << 32);
    *(u64*)&g_xh[idx * 4] = h;
    *(u64*)&g_xl[idx * 4] = l;
}

__global__ void prep_wt_kernel(const float* __restrict__ src,
                               __nv_bfloat16* __restrict__ dsth,
                               __nv_bfloat16* __restrict__ dstl, int N)
{
    __shared__ float t[32][33];
    int n0 = blockIdx.x * 32, k0 = blockIdx.y * 32;
    int tx = threadIdx.x, ty = threadIdx.y;   // (32, 8)
#pragma unroll
    for (int i = 0; i < 4; i++)
        t[ty + 8 * i][tx] = src[(size_t)(k0 + ty + 8 * i) * N + n0 + tx];
    __syncthreads();
#pragma unroll
    for (int i = 0; i < 4; i++) {
        int n = n0 + ty + 8 * i;
        float v = t[tx][ty + 8 * i];
        __nv_bfloat16 h = __float2bfloat16(v);
        dsth[(size_t)n * 512 + k0 + tx] = h;
        dstl[(size_t)n * 512 + k0 + tx] = __float2bfloat16(v - __bfloat162float(h));
    }
}

// bias table: e(i,j) for all pairs; one block per i, 8 j's per thread
__global__ void bias_kernel(const float* __restrict__ pos) {
    int i = blockIdx.x;
    int j0 = threadIdx.x * 8;
    float xi = pos[2 * i], yi = pos[2 * i + 1];
    __half h[8];
#pragma unroll
    for (int j = 0; j < 8; j++) {
        float xj = pos[2 * (j0 + j)], yj = pos[2 * (j0 + j) + 1];
        float dx = fabsf(xi - xj); dx = fminf(dx, 1.0f - dx);
        float dy = fabsf(yi - yj); dy = fminf(dy, 1.0f - dy);
        h[j] = __float2half(dx * dx + dy * dy);
    }
    *(uint4*)&g_eb[(size_t)i * NN + j0] = *(uint4*)h;
}

// ---------------------------------------------------------------------------
// Tensor-core GEMM body (ldmatrix fragment loads).
// ---------------------------------------------------------------------------
#define ARR  (128*GP*2)
#define SM_AHI 0
#define SM_ALO ARR
#define SM_BHI (2*ARR)
#define SM_BLO (3*ARR)
#define GEMM_SMEM_BYTES (4*ARR)   // 73728

template<int MT>
__device__ __forceinline__ void gemm_mma_body_bf16(
    const __nv_bfloat16* __restrict__ ah, const __nv_bfloat16* __restrict__ al,
    const __nv_bfloat16* __restrict__ bth, const __nv_bfloat16* __restrict__ btl,
    char* smc, float cacc[MT][4][4])
{
    __nv_bfloat16* Ahi = (__nv_bfloat16*)(smc + SM_AHI);
    __nv_bfloat16* Alo = (__nv_bfloat16*)(smc + SM_ALO);
    __nv_bfloat16* Bhi = (__nv_bfloat16*)(smc + SM_BHI);
    __nv_bfloat16* Blo = (__nv_bfloat16*)(smc + SM_BLO);

    const int tid = threadIdx.x;
    const int w = tid >> 5, lane = tid & 31;
    const int wm = w >> 2, wn = w & 3;
    const u32 sAhi = smem_u32(Ahi), sAlo = smem_u32(Alo);
    const u32 sBhi = smem_u32(Bhi), sBlo = smem_u32(Blo);
    const u32 aoff = lane_a_off(lane), boff = lane_b_off(lane);

#pragma unroll
    for (int mt = 0; mt < MT; mt++)
#pragma unroll
        for (int nt = 0; nt < 4; nt++)
#pragma unroll
            for (int j = 0; j < 4; j++) cacc[mt][nt][j] = 0.f;

    for (int c = 0; c < 8; c++) {
        const int k0 = c * 64;
        if (c) __syncthreads();
#pragma unroll
        for (int s = 0; s < MT; s++) {
            int idx = tid + 256 * s;
            int r = idx >> 3, seg = (idx & 7) * 8;
            *(uint4*)&Ahi[r * GP + seg] = *(const uint4*)&ah[(size_t)r * 512 + k0 + seg];
            *(uint4*)&Alo[r * GP + seg] = *(const uint4*)&al[(size_t)r * 512 + k0 + seg];
        }
#pragma unroll
        for (int s = 0; s < 4; s++) {
            int idx = tid + 256 * s;
            int r = idx >> 3, seg = (idx & 7) * 8;
            *(uint4*)&Bhi[r * GP + seg] = *(const uint4*)&bth[(size_t)r * 512 + k0 + seg];
            *(uint4*)&Blo[r * GP + seg] = *(const uint4*)&btl[(size_t)r * 512 + k0 + seg];
        }
        __syncthreads();

#pragma unroll
        for (int ks = 0; ks < 4; ks++) {
            const u32 kbyte = ks * 32;
            u32 bh[4][2], bl[4][2];
#pragma unroll
            for (int np = 0; np < 2; np++) {
                u32 rb = (u32)((wn * 32 + np * 16) * GP * 2) + kbyte + boff;
                ldsm4(bh[2*np][0], bh[2*np][1], bh[2*np+1][0], bh[2*np+1][1], sBhi + rb);
                ldsm4(bl[2*np][0], bl[2*np][1], bl[2*np+1][0], bl[2*np+1][1], sBlo + rb);
            }
#pragma unroll
            for (int mt = 0; mt < MT; mt++) {
                u32 ra = (u32)((wm * (MT * 16) + mt * 16) * GP * 2) + kbyte + aoff;
                u32 ah0, ah1, ah2, ah3, al0, al1, al2, al3;
                ldsm4(ah0, ah1, ah2, ah3, sAhi + ra);
                ldsm4(al0, al1, al2, al3, sAlo + ra);
#pragma unroll
                for (int nt = 0; nt < 4; nt++) {
                    mma16816(cacc[mt][nt], ah0, ah1, ah2, ah3, bh[nt][0], bh[nt][1]);
                    mma16816(cacc[mt][nt], ah0, ah1, ah2, ah3, bl[nt][0], bl[nt][1]);
                    mma16816(cacc[mt][nt], al0, al1, al2, al3, bh[nt][0], bh[nt][1]);
                }
            }
        }
    }
}

// ---------------------------------------------------------------------------
// Kernel: QKV GEMM -> q/k/v fp32 scatter
// ---------------------------------------------------------------------------
__global__ __launch_bounds__(256, 2) void qkv_gemm_kernel(const float* __restrict__ bin)
{
    extern __shared__ char smc[];
    const int row0 = blockIdx.y * 128;
    const int col0 = blockIdx.x * 128;
    const int lane = threadIdx.x & 31;
    const int w = threadIdx.x >> 5;
    const int qr = lane >> 2, qc = lane & 3;
    const int wm = w >> 2, wn = w & 3;

    float cacc[4][4][4];
    gemm_mma_body_bf16<4>(g_xh + (size_t)row0 * 512, g_xl + (size_t)row0 * 512,
                          g_winh + (size_t)col0 * 512, g_winl + (size_t)col0 * 512,
                          smc, cacc);

#pragma unroll
    for (int mt = 0; mt < 4; mt++) {
        int grow = row0 + wm * 64 + mt * 16 + qr;
        int bi = grow >> 11, ni = grow & 2047;
#pragma unroll
        for (int nt = 0; nt < 4; nt++) {
            int c0 = col0 + wn * 32 + nt * 8 + 2 * qc;
            int three = c0 >> 9;
            int head  = (c0 >> 6) & 7;
            float* dst = (three == 0) ? g_q : (three == 1) ? g_k : g_v;
            float* base = dst + (((size_t)bi * HH + head) * NN) * DD + (c0 & 63);
            float2 bv = *(const float2*)(bin + c0);
            float2 r0 = make_float2(cacc[mt][nt][0] + bv.x, cacc[mt][nt][1] + bv.y);
            float2 r1 = make_float2(cacc[mt][nt][2] + bv.x, cacc[mt][nt][3] + bv.y);
            *(float2*)&base[(size_t)ni * 64] = r0;
            *(float2*)&base[(size_t)(ni + 8) * 64] = r1;
        }
    }
}

// ---------------------------------------------------------------------------
// Kernel: LayerNorm q,k -> bf16 hi/lo
// ---------------------------------------------------------------------------
__global__ void ln_qk_kernel(const float* __restrict__ qn_w, const float* __restrict__ qn_b,
                             const float* __restrict__ kn_w, const float* __restrict__ kn_b)
{
    const int ROWS = BHD * NN;
    int gid = blockIdx.x * 8 + (threadIdx.x >> 5);
    int lane = threadIdx.x & 31;
    if (gid >= 2 * ROWS) return;
    bool isq = gid < ROWS;
    int r = isq ? gid : gid - ROWS;
    const float* buf = isq ? g_q : g_k;
    __nv_bfloat16* oh = isq ? g_qh : g_kh;
    __nv_bfloat16* ol = isq ? g_ql : g_kl;
    const float* w = isq ? qn_w : kn_w;
    const float* bb = isq ? qn_b : kn_b;

    float x0 = buf[(size_t)r * 64 + lane];
    float x1 = buf[(size_t)r * 64 + 32 + lane];
    float s = x0 + x1;
#pragma unroll
    for (int off = 16; off >= 1; off >>= 1) s += __shfl_xor_sync(0xffffffffu, s, off);
    float mu = s * (1.0f / 64.0f);
    float d0 = x0 - mu, d1 = x1 - mu;
    float v = d0 * d0 + d1 * d1;
#pragma unroll
    for (int off = 16; off >= 1; off >>= 1) v += __shfl_xor_sync(0xffffffffu, v, off);
    float inv = rsqrtf(v * (1.0f / 64.0f) + 1e-5f);
    float y0 = d0 * inv * w[lane] + bb[lane];
    float y1 = d1 * inv * w[lane + 32] + bb[lane + 32];
    __nv_bfloat16 h0 = __float2bfloat16(y0);
    __nv_bfloat16 h1 = __float2bfloat16(y1);
    oh[(size_t)r * 64 + lane]      = h0;
    oh[(size_t)r * 64 + 32 + lane] = h1;
    ol[(size_t)r * 64 + lane]      = __float2bfloat16(y0 - __bfloat162float(h0));
    ol[(size_t)r * 64 + 32 + lane] = __float2bfloat16(y1 - __bfloat162float(h1));
}

// ---------------------------------------------------------------------------
// Kernel: v [bh][n][64] fp32 -> vt [bh][d][n] bf16 hi/lo
// ---------------------------------------------------------------------------
__global__ void vt_kernel()
{
    __shared__ float ts[64][65];
    int bh = blockIdx.y;
    int n0 = blockIdx.x * 64;
    int tid = threadIdx.x;
    const float* vb = g_v + (size_t)bh * NN * DD + (size_t)n0 * 64;

#pragma unroll
    for (int i = 0; i < 4; i++) {
        int f4 = tid + 256 * i;
        int r = f4 >> 4, c4 = (f4 & 15) * 4;
        float4 v = *(const float4*)(vb + (size_t)r * 64 + c4);
        ts[r][c4 + 0] = v.x; ts[r][c4 + 1] = v.y;
        ts[r][c4 + 2] = v.z; ts[r][c4 + 3] = v.w;
    }
    __syncthreads();

    int d = tid >> 2, ns = (tid & 3) * 16;
    __nv_bfloat16* oh = g_vth + (size_t)bh * DD * NN + (size_t)d * NN + n0 + ns;
    __nv_bfloat16* ol = g_vtl + (size_t)bh * DD * NN + (size_t)d * NN + n0 + ns;
#pragma unroll
    for (int j = 0; j < 8; j++) {
        float a = ts[ns + 2 * j][d], b = ts[ns + 2 * j + 1][d];
        *(u32*)&oh[2 * j] = pack_hi2(a, b);
        *(u32*)&ol[2 * j] = pack_lo2(a, b);
    }
}

// ---------------------------------------------------------------------------
// Kernel: flash attention (precomputed fp16 bias, ex2.approx softmax)
// ---------------------------------------------------------------------------
#define QS GP
#define SM_QHI   0
#define SM_QLO   (SM_QHI  + 128*QS*2)
#define SM_KHI   (SM_QLO  + 128*QS*2)
#define SM_KLO   (SM_KHI  + 64*QS*2)
#define SM_VTHI  (SM_KLO  + 64*QS*2)
#define SM_VTLO  (SM_VTHI + 64*QS*2)
#define ATTN_SMEM_BYTES (SM_VTLO + 64*QS*2)

__global__ __launch_bounds__(256, 2) void attn_kernel()
{
    extern __shared__ char smc[];
    __nv_bfloat16* Qhi  = (__nv_bfloat16*)(smc + SM_QHI);
    __nv_bfloat16* Qlo  = (__nv_bfloat16*)(smc + SM_QLO);
    __nv_bfloat16* Khi  = (__nv_bfloat16*)(smc + SM_KHI);
    __nv_bfloat16* Klo  = (__nv_bfloat16*)(smc + SM_KLO);
    __nv_bfloat16* Vthi = (__nv_bfloat16*)(smc + SM_VTHI);
    __nv_bfloat16* Vtlo = (__nv_bfloat16*)(smc + SM_VTLO);

    const int tid = threadIdx.x;
    const int w = tid >> 5, lane = tid & 31;
    const int qr = lane >> 2, qc = lane & 3;
    const int q0 = blockIdx.x * 128;
    const int bh = blockIdx.y;
    const int bi = bh >> 3, head = bh & 7;

    const u32 sQhi = smem_u32(Qhi), sQlo = smem_u32(Qlo);
    const u32 sKhi = smem_u32(Khi), sKlo = smem_u32(Klo);
    const u32 sVhi = smem_u32(Vthi), sVlo = smem_u32(Vtlo);
    const u32 aoff = lane_a_off(lane), boff = lane_b_off(lane);

    const __nv_bfloat16* qbh = g_qh + (size_t)bh * NN * DD + (size_t)q0 * 64;
    const __nv_bfloat16* qbl = g_ql + (size_t)bh * NN * DD + (size_t)q0 * 64;
    const __nv_bfloat16* kbh = g_kh + (size_t)bh * NN * DD;
    const __nv_bfloat16* kbl = g_kl + (size_t)bh * NN * DD;
    const __nv_bfloat16* vbh = g_vth + (size_t)bh * DD * NN;
    const __nv_bfloat16* vbl = g_vtl + (size_t)bh * DD * NN;

#pragma unroll
    for (int s = 0; s < 4; s++) {
        int idx = tid + 256 * s;
        int r = idx >> 3, seg = (idx & 7) * 8;
        *(uint4*)&Qhi[r * QS + seg] = *(const uint4*)&qbh[(size_t)r * 64 + seg];
        *(uint4*)&Qlo[r * QS + seg] = *(const uint4*)&qbl[(size_t)r * 64 + seg];
    }

    const int lrow0 = w * 16 + qr;
    const __half* eb0 = g_eb + (size_t)(q0 + lrow0) * NN;
    const __half* eb1 = g_eb + (size_t)(q0 + lrow0 + 8) * NN;

    float oacc[8][4];
#pragma unroll
    for (int i = 0; i < 8; i++)
#pragma unroll
        for (int j = 0; j < 4; j++) oacc[i][j] = 0.f;
    float lsum0 = 0.f, lsum1 = 0.f;
    float sacc[8][4];

    for (int kt = 0; kt < 32; kt++) {
        const int k0 = kt * 64;
        __syncthreads();
#pragma unroll
        for (int s = 0; s < 2; s++) {
            int idx = tid + 256 * s;
            int r = idx >> 3, seg = (idx & 7) * 8;
            *(uint4*)&Khi[r * QS + seg]  = *(const uint4*)&kbh[(size_t)(k0 + r) * 64 + seg];
            *(uint4*)&Klo[r * QS + seg]  = *(const uint4*)&kbl[(size_t)(k0 + r) * 64 + seg];
            *(uint4*)&Vthi[r * QS + seg] = *(const uint4*)&vbh[(size_t)r * NN + k0 + seg];
            *(uint4*)&Vtlo[r * QS + seg] = *(const uint4*)&vbl[(size_t)r * NN + k0 + seg];
        }
        __syncthreads();

        // ---- S = Q K^T ----
#pragma unroll
        for (int i = 0; i < 8; i++)
#pragma unroll
            for (int j = 0; j < 4; j++) sacc[i][j] = 0.f;

#pragma unroll
        for (int ks = 0; ks < 4; ks++) {
            const u32 kbyte = ks * 32;
            u32 ra = (u32)(w * 16 * QS * 2) + kbyte + aoff;
            u32 qh0, qh1, qh2, qh3, ql0, ql1, ql2, ql3;
            ldsm4(qh0, qh1, qh2, qh3, sQhi + ra);
            ldsm4(ql0, ql1, ql2, ql3, sQlo + ra);
#pragma unroll
            for (int np = 0; np < 4; np++) {
                u32 rb = (u32)(np * 16 * QS * 2) + kbyte + boff;
                u32 kh0a, kh1a, kh0b, kh1b, kl0a, kl1a, kl0b, kl1b;
                ldsm4(kh0a, kh1a, kh0b, kh1b, sKhi + rb);
                ldsm4(kl0a, kl1a, kl0b, kl1b, sKlo + rb);
                mma16816(sacc[2*np],   qh0, qh1, qh2, qh3, kh0a, kh1a);
                mma16816(sacc[2*np],   qh0, qh1, qh2, qh3, kl0a, kl1a);
                mma16816(sacc[2*np],   ql0, ql1, ql2, ql3, kh0a, kh1a);
                mma16816(sacc[2*np+1], qh0, qh1, qh2, qh3, kh0b, kh1b);
                mma16816(sacc[2*np+1], qh0, qh1, qh2, qh3, kl0b, kl1b);
                mma16816(sacc[2*np+1], ql0, ql1, ql2, ql3, kh0b, kh1b);
            }
        }

        // ---- softmax (fixed max 8, precomputed fp16 bias) ----
        // p = ex2( s*(log2e/8) - e*log2e - 8*log2e )
#pragma unroll
        for (int nt = 0; nt < 8; nt++) {
            int cb = nt * 8 + 2 * qc;
            float2 e0 = __half22float2(*(const __half2*)&eb0[k0 + cb]);
            float2 e1 = __half22float2(*(const __half2*)&eb1[k0 + cb]);
            float p0 = ex2f(fmaf(e0.x, -1.44269504f,
                            fmaf(sacc[nt][0], 0.18033688f, -11.54156036f)));
            float p1 = ex2f(fmaf(e0.y, -1.44269504f,
                            fmaf(sacc[nt][1], 0.18033688f, -11.54156036f)));
            float p2 = ex2f(fmaf(e1.x, -1.44269504f,
                            fmaf(sacc[nt][2], 0.18033688f, -11.54156036f)));
            float p3 = ex2f(fmaf(e1.y, -1.44269504f,
                            fmaf(sacc[nt][3], 0.18033688f, -11.54156036f)));
            lsum0 += p0 + p1;
            lsum1 += p2 + p3;
            sacc[nt][0] = p0; sacc[nt][1] = p1; sacc[nt][2] = p2; sacc[nt][3] = p3;
        }

        // ---- O += P V ----
#pragma unroll
        for (int ks = 0; ks < 4; ks++) {
            const u32 kbyte = ks * 32;
            u32 ah0 = pack_hi2(sacc[2 * ks][0],     sacc[2 * ks][1]);
            u32 ah1 = pack_hi2(sacc[2 * ks][2],     sacc[2 * ks][3]);
            u32 ah2 = pack_hi2(sacc[2 * ks + 1][0], sacc[2 * ks + 1][1]);
            u32 ah3 = pack_hi2(sacc[2 * ks + 1][2], sacc[2 * ks + 1][3]);
            u32 al0 = pack_lo2(sacc[2 * ks][0],     sacc[2 * ks][1]);
            u32 al1 = pack_lo2(sacc[2 * ks][2],     sacc[2 * ks][3]);
            u32 al2 = pack_lo2(sacc[2 * ks + 1][0], sacc[2 * ks + 1][1]);
            u32 al3 = pack_lo2(sacc[2 * ks + 1][2], sacc[2 * ks + 1][3]);
#pragma unroll
            for (int np = 0; np < 4; np++) {
                u32 rb = (u32)(np * 16 * QS * 2) + kbyte + boff;
                u32 vh0a, vh1a, vh0b, vh1b, vl0a, vl1a, vl0b, vl1b;
                ldsm4(vh0a, vh1a, vh0b, vh1b, sVhi + rb);
                ldsm4(vl0a, vl1a, vl0b, vl1b, sVlo + rb);
                mma16816(oacc[2*np],   ah0, ah1, ah2, ah3, vh0a, vh1a);
                mma16816(oacc[2*np],   ah0, ah1, ah2, ah3, vl0a, vl1a);
                mma16816(oacc[2*np],   al0, al1, al2, al3, vh0a, vh1a);
                mma16816(oacc[2*np+1], ah0, ah1, ah2, ah3, vh0b, vh1b);
                mma16816(oacc[2*np+1], ah0, ah1, ah2, ah3, vl0b, vl1b);
                mma16816(oacc[2*np+1], al0, al1, al2, al3, vh0b, vh1b);
            }
        }
    }

#pragma unroll
    for (int off = 1; off <= 2; off <<= 1) {
        lsum0 += __shfl_xor_sync(0xffffffffu, lsum0, off);
        lsum1 += __shfl_xor_sync(0xffffffffu, lsum1, off);
    }
    float inv0 = 1.0f / lsum0, inv1 = 1.0f / lsum1;

    __nv_bfloat16* obh = g_atth + ((size_t)bi * NN + q0) * DIM + head * 64;
    __nv_bfloat16* obl = g_attl + ((size_t)bi * NN + q0) * DIM + head * 64;
#pragma unroll
    for (int nt = 0; nt < 8; nt++) {
        int cb = nt * 8 + 2 * qc;
        float a0 = oacc[nt][0] * inv0, a1 = oacc[nt][1] * inv0;
        float b0 = oacc[nt][2] * inv1, b1 = oacc[nt][3] * inv1;
        *(u32*)&obh[(size_t)lrow0 * DIM + cb]       = pack_hi2(a0, a1);
        *(u32*)&obl[(size_t)lrow0 * DIM + cb]       = pack_lo2(a0, a1);
        *(u32*)&obh[(size_t)(lrow0 + 8) * DIM + cb] = pack_hi2(b0, b1);
        *(u32*)&obl[(size_t)(lrow0 + 8) * DIM + cb] = pack_lo2(b0, b1);
    }
}

// ---------------------------------------------------------------------------
// Kernel: output GEMM — 64-row tiles, grid (4, 64) = 256 CTAs
// ---------------------------------------------------------------------------
__global__ __launch_bounds__(256, 2) void out_gemm_kernel(
    const float* __restrict__ bout, float* __restrict__ out)
{
    extern __shared__ char smc[];
    const int row0 = blockIdx.y * 64;
    const int col0 = blockIdx.x * 128;
    const int lane = threadIdx.x & 31;
    const int w = threadIdx.x >> 5;
    const int qr = lane >> 2, qc = lane & 3;
    const int wm = w >> 2, wn = w & 3;

    float cacc[2][4][4];
    gemm_mma_body_bf16<2>(g_atth + (size_t)row0 * 512, g_attl + (size_t)row0 * 512,
                          g_wouth + (size_t)col0 * 512, g_woutl + (size_t)col0 * 512,
                          smc, cacc);

#pragma unroll
    for (int mt = 0; mt < 2; mt++) {
        int grow = row0 + wm * 32 + mt * 16 + qr;
#pragma unroll
        for (int nt = 0; nt < 4; nt++) {
            int c0 = col0 + wn * 32 + nt * 8 + 2 * qc;
            float2 bv = *(const float2*)(bout + c0);
            float2 r0 = make_float2(cacc[mt][nt][0] + bv.x, cacc[mt][nt][1] + bv.y);
            float2 r1 = make_float2(cacc[mt][nt][2] + bv.x, cacc[mt][nt][3] + bv.y);
            *(float2*)&out[(size_t)grow * 512 + c0] = r0;
            *(float2*)&out[(size_t)(grow + 8) * 512 + c0] = r1;
        }
    }
}

// ---------------------------------------------------------------------------
extern "C" void kernel_launch(void* const* d_in, const int* in_sizes, int n_in,
                              void* d_out, int out_size)
{
    const float* x    = (const float*)d_in[0];
    const float* pos  = (const float*)d_in[1];
    const float* W_in = (const float*)d_in[2];
    const float* b_in = (const float*)d_in[3];
    const float* qn_w = (const float*)d_in[4];
    const float* qn_b = (const float*)d_in[5];
    const float* kn_w = (const float*)d_in[6];
    const float* kn_b = (const float*)d_in[7];
    const float* W_out= (const float*)d_in[8];
    const float* b_out= (const float*)d_in[9];
    float* out = (float*)d_out;

    cudaFuncSetAttribute(qkv_gemm_kernel, cudaFuncAttributeMaxDynamicSharedMemorySize, GEMM_SMEM_BYTES);
    cudaFuncSetAttribute(out_gemm_kernel, cudaFuncAttributeMaxDynamicSharedMemorySize, GEMM_SMEM_BYTES);
    cudaFuncSetAttribute(attn_kernel, cudaFuncAttributeMaxDynamicSharedMemorySize, ATTN_SMEM_BYTES);

    __nv_bfloat16 *winh, *winl, *wouth, *woutl;
    cudaGetSymbolAddress((void**)&winh, g_winh);
    cudaGetSymbolAddress((void**)&winl, g_winl);
    cudaGetSymbolAddress((void**)&wouth, g_wouth);
    cudaGetSymbolAddress((void**)&woutl, g_woutl);

    prep_x_kernel<<<BN * DIM / 4 / 256, 256>>>(x);
    prep_wt_kernel<<<dim3(1536 / 32, 512 / 32), dim3(32, 8)>>>(W_in, winh, winl, 1536);
    prep_wt_kernel<<<dim3(512 / 32, 512 / 32), dim3(32, 8)>>>(W_out, wouth, woutl, 512);
    bias_kernel<<<NN, 256>>>(pos);

    qkv_gemm_kernel<<<dim3(12, 32), 256, GEMM_SMEM_BYTES>>>(b_in);
    ln_qk_kernel<<<(2 * BHD * NN) / 8, 256>>>(qn_w, qn_b, kn_w, kn_b);
    vt_kernel<<<dim3(NN / 64, BHD), 256>>>();
    attn_kernel<<<dim3(16, 16), 256, ATTN_SMEM_BYTES>>>();
    out_gemm_kernel<<<dim3(4, 64), 256, GEMM_SMEM_BYTES>>>(b_out, out);
}

// round 16
// speedup vs baseline: 1.0366x; 1.0366x over previous
#include <cuda_runtime.h>
#include <cuda_bf16.h>
#include <cuda_fp16.h>
#include <math.h>
#include <stdint.h>

#define BB   2
#define NN   2048
#define DIM  512
#define HH   8
#define DD   64
#define BN   (BB*NN)    // 4096
#define BHD  (BB*HH)    // 16

typedef unsigned long long u64;
typedef unsigned int u32;

// fp32 scratch (qkv output; q,k consumed by LN, v by transpose)
__device__ float g_q[BHD*NN*DD];
__device__ float g_k[BHD*NN*DD];
__device__ float g_v[BHD*NN*DD];

// bf16 hi/lo scratch
__device__ __nv_bfloat16 g_xh[BN*DIM],    g_xl[BN*DIM];
__device__ __nv_bfloat16 g_winh[1536*512], g_winl[1536*512];   // [n][k]
__device__ __nv_bfloat16 g_wouth[512*512], g_woutl[512*512];   // [n][k]
__device__ __nv_bfloat16 g_qh[BHD*NN*DD], g_ql[BHD*NN*DD];
__device__ __nv_bfloat16 g_kh[BHD*NN*DD], g_kl[BHD*NN*DD];
__device__ __nv_bfloat16 g_vth[BHD*DD*NN], g_vtl[BHD*DD*NN];   // [bh][d][n]
__device__ __nv_bfloat16 g_atth[BN*DIM],  g_attl[BN*DIM];

// positional bias table: e(i,j) = wrapped squared distance, fp16 (8 MB)
__device__ __half g_eb[(size_t)NN*NN];

// ---------------------------------------------------------------------------
// helpers
// ---------------------------------------------------------------------------
__device__ __forceinline__ void mma16816(float* c,
    u32 a0, u32 a1, u32 a2, u32 a3, u32 b0, u32 b1)
{
    asm volatile(
        "mma.sync.aligned.m16n8k16.row.col.f32.bf16.bf16.f32 "
        "{%0,%1,%2,%3}, {%4,%5,%6,%7}, {%8,%9}, {%0,%1,%2,%3};"
        : "+f"(c[0]), "+f"(c[1]), "+f"(c[2]), "+f"(c[3])
        : "r"(a0), "r"(a1), "r"(a2), "r"(a3), "r"(b0), "r"(b1));
}
__device__ __forceinline__ void ldsm4(u32& r0, u32& r1, u32& r2, u32& r3, u32 addr) {
    asm volatile("ldmatrix.sync.aligned.m8n8.x4.shared.b16 {%0,%1,%2,%3}, [%4];"
        : "=r"(r0), "=r"(r1), "=r"(r2), "=r"(r3) : "r"(addr));
}
__device__ __forceinline__ float ex2f(float x) {
    float y;
    asm("ex2.approx.f32 %0, %1;" : "=f"(y) : "f"(x));
    return y;
}
__device__ __forceinline__ u32 pack_bf(__nv_bfloat16 a, __nv_bfloat16 b) {
    return (u32)__bfloat16_as_ushort(a) | ((u32)__bfloat16_as_ushort(b) << 16);
}
__device__ __forceinline__ u32 pack_hi2(float x, float y) {
    return pack_bf(__float2bfloat16(x), __float2bfloat16(y));
}
__device__ __forceinline__ u32 pack_lo2(float x, float y) {
    __nv_bfloat16 hx = __float2bfloat16(x), hy = __float2bfloat16(y);
    return pack_bf(__float2bfloat16(x - __bfloat162float(hx)),
                   __float2bfloat16(y - __bfloat162float(hy)));
}
__device__ __forceinline__ u32 smem_u32(const void* p) {
    u32 a;
    asm("{ .reg .u64 t; cvta.to.shared.u64 t, %1; cvt.u32.u64 %0, t; }"
        : "=r"(a) : "l"(p));
    return a;
}

#define GP 72
__device__ __forceinline__ u32 lane_a_off(int lane) {
    int m4 = lane >> 3, r8 = lane & 7;
    return (u32)((((m4 & 1) * 8 + r8) * GP + (m4 >> 1) * 8) * 2);
}
__device__ __forceinline__ u32 lane_b_off(int lane) {
    int m4 = lane >> 3, r8 = lane & 7;
    return (u32)((((m4 >> 1) * 8 + r8) * GP + (m4 & 1) * 8) * 2);
}

// ---------------------------------------------------------------------------
// prep kernels
// ---------------------------------------------------------------------------
__global__ void prep_x_kernel(const float* __restrict__ x) {
    int idx = blockIdx.x * 256 + threadIdx.x;
    float4 v = ((const float4*)x)[idx];
    u64 h = (u64)pack_hi2(v.x, v.y) | ((u64)pack_hi2(v.z, v.w) << 32);
    u64 l = (u64)pack_lo2(v.x, v.y) | ((u64)pack_lo2(v.z, v.w) << 32);
    *(u64*)&g_xh[idx * 4] = h;
    *(u64*)&g_xl[idx * 4] = l;
}

__global__ void prep_wt_kernel(const float* __restrict__ src,
                               __nv_bfloat16* __restrict__ dsth,
                               __nv_bfloat16* __restrict__ dstl, int N)
{
    __shared__ float t[32][33];
    int n0 = blockIdx.x * 32, k0 = blockIdx.y * 32;
    int tx = threadIdx.x, ty = threadIdx.y;   // (32, 8)
#pragma unroll
    for (int i = 0; i < 4; i++)
        t[ty + 8 * i][tx] = src[(size_t)(k0 + ty + 8 * i) * N + n0 + tx];
    __syncthreads();
#pragma unroll
    for (int i = 0; i < 4; i++) {
        int n = n0 + ty + 8 * i;
        float v = t[tx][ty + 8 * i];
        __nv_bfloat16 h = __float2bfloat16(v);
        dsth[(size_t)n * 512 + k0 + tx] = h;
        dstl[(size_t)n * 512 + k0 + tx] = __float2bfloat16(v - __bfloat162float(h));
    }
}

// bias table: pos staged in smem, 16 rows per block, conflict-free LDS.128,
// coalesced half2 stores.
__global__ void bias_kernel(const float* __restrict__ pos) {
    __shared__ float2 ps[NN];
    const int tid = threadIdx.x;
    for (int s = tid; s < NN; s += 256)
        ps[s] = ((const float2*)pos)[s];
    __syncthreads();

    const int i0 = blockIdx.x * 16;
#pragma unroll
    for (int r = 0; r < 16; r++) {
        int i = i0 + r;
        float xi = ps[i].x, yi = ps[i].y;
#pragma unroll
        for (int jj = 0; jj < 4; jj++) {
            int j = 2 * tid + 512 * jj;
            float4 pj = *(const float4*)&ps[j];   // (x_j, y_j, x_j1, y_j1)
            float dx0 = fabsf(xi - pj.x); dx0 = fminf(dx0, 1.0f - dx0);
            float dy0 = fabsf(yi - pj.y); dy0 = fminf(dy0, 1.0f - dy0);
            float dx1 = fabsf(xi - pj.z); dx1 = fminf(dx1, 1.0f - dx1);
            float dy1 = fabsf(yi - pj.w); dy1 = fminf(dy1, 1.0f - dy1);
            __half2 e = __floats2half2_rn(dx0 * dx0 + dy0 * dy0,
                                          dx1 * dx1 + dy1 * dy1);
            *(__half2*)&g_eb[(size_t)i * NN + j] = e;
        }
    }
}

// ---------------------------------------------------------------------------
// Tensor-core GEMM body (ldmatrix fragment loads).
// ---------------------------------------------------------------------------
#define ARR  (128*GP*2)
#define SM_AHI 0
#define SM_ALO ARR
#define SM_BHI (2*ARR)
#define SM_BLO (3*ARR)
#define GEMM_SMEM_BYTES (4*ARR)   // 73728

template<int MT>
__device__ __forceinline__ void gemm_mma_body_bf16(
    const __nv_bfloat16* __restrict__ ah, const __nv_bfloat16* __restrict__ al,
    const __nv_bfloat16* __restrict__ bth, const __nv_bfloat16* __restrict__ btl,
    char* smc, float cacc[MT][4][4])
{
    __nv_bfloat16* Ahi = (__nv_bfloat16*)(smc + SM_AHI);
    __nv_bfloat16* Alo = (__nv_bfloat16*)(smc + SM_ALO);
    __nv_bfloat16* Bhi = (__nv_bfloat16*)(smc + SM_BHI);
    __nv_bfloat16* Blo = (__nv_bfloat16*)(smc + SM_BLO);

    const int tid = threadIdx.x;
    const int w = tid >> 5, lane = tid & 31;
    const int wm = w >> 2, wn = w & 3;
    const u32 sAhi = smem_u32(Ahi), sAlo = smem_u32(Alo);
    const u32 sBhi = smem_u32(Bhi), sBlo = smem_u32(Blo);
    const u32 aoff = lane_a_off(lane), boff = lane_b_off(lane);

#pragma unroll
    for (int mt = 0; mt < MT; mt++)
#pragma unroll
        for (int nt = 0; nt < 4; nt++)
#pragma unroll
            for (int j = 0; j < 4; j++) cacc[mt][nt][j] = 0.f;

    for (int c = 0; c < 8; c++) {
        const int k0 = c * 64;
        if (c) __syncthreads();
#pragma unroll
        for (int s = 0; s < MT; s++) {
            int idx = tid + 256 * s;
            int r = idx >> 3, seg = (idx & 7) * 8;
            *(uint4*)&Ahi[r * GP + seg] = *(const uint4*)&ah[(size_t)r * 512 + k0 + seg];
            *(uint4*)&Alo[r * GP + seg] = *(const uint4*)&al[(size_t)r * 512 + k0 + seg];
        }
#pragma unroll
        for (int s = 0; s < 4; s++) {
            int idx = tid + 256 * s;
            int r = idx >> 3, seg = (idx & 7) * 8;
            *(uint4*)&Bhi[r * GP + seg] = *(const uint4*)&bth[(size_t)r * 512 + k0 + seg];
            *(uint4*)&Blo[r * GP + seg] = *(const uint4*)&btl[(size_t)r * 512 + k0 + seg];
        }
        __syncthreads();

#pragma unroll
        for (int ks = 0; ks < 4; ks++) {
            const u32 kbyte = ks * 32;
            u32 bh[4][2], bl[4][2];
#pragma unroll
            for (int np = 0; np < 2; np++) {
                u32 rb = (u32)((wn * 32 + np * 16) * GP * 2) + kbyte + boff;
                ldsm4(bh[2*np][0], bh[2*np][1], bh[2*np+1][0], bh[2*np+1][1], sBhi + rb);
                ldsm4(bl[2*np][0], bl[2*np][1], bl[2*np+1][0], bl[2*np+1][1], sBlo + rb);
            }
#pragma unroll
            for (int mt = 0; mt < MT; mt++) {
                u32 ra = (u32)((wm * (MT * 16) + mt * 16) * GP * 2) + kbyte + aoff;
                u32 ah0, ah1, ah2, ah3, al0, al1, al2, al3;
                ldsm4(ah0, ah1, ah2, ah3, sAhi + ra);
                ldsm4(al0, al1, al2, al3, sAlo + ra);
#pragma unroll
                for (int nt = 0; nt < 4; nt++) {
                    mma16816(cacc[mt][nt], ah0, ah1, ah2, ah3, bh[nt][0], bh[nt][1]);
                    mma16816(cacc[mt][nt], ah0, ah1, ah2, ah3, bl[nt][0], bl[nt][1]);
                    mma16816(cacc[mt][nt], al0, al1, al2, al3, bh[nt][0], bh[nt][1]);
                }
            }
        }
    }
}

// ---------------------------------------------------------------------------
// Kernel: QKV GEMM -> q/k/v fp32 scatter
// ---------------------------------------------------------------------------
__global__ __launch_bounds__(256, 2) void qkv_gemm_kernel(const float* __restrict__ bin)
{
    extern __shared__ char smc[];
    const int row0 = blockIdx.y * 128;
    const int col0 = blockIdx.x * 128;
    const int lane = threadIdx.x & 31;
    const int w = threadIdx.x >> 5;
    const int qr = lane >> 2, qc = lane & 3;
    const int wm = w >> 2, wn = w & 3;

    float cacc[4][4][4];
    gemm_mma_body_bf16<4>(g_xh + (size_t)row0 * 512, g_xl + (size_t)row0 * 512,
                          g_winh + (size_t)col0 * 512, g_winl + (size_t)col0 * 512,
                          smc, cacc);

#pragma unroll
    for (int mt = 0; mt < 4; mt++) {
        int grow = row0 + wm * 64 + mt * 16 + qr;
        int bi = grow >> 11, ni = grow & 2047;
#pragma unroll
        for (int nt = 0; nt < 4; nt++) {
            int c0 = col0 + wn * 32 + nt * 8 + 2 * qc;
            int three = c0 >> 9;
            int head  = (c0 >> 6) & 7;
            float* dst = (three == 0) ? g_q : (three == 1) ? g_k : g_v;
            float* base = dst + (((size_t)bi * HH + head) * NN) * DD + (c0 & 63);
            float2 bv = *(const float2*)(bin + c0);
            float2 r0 = make_float2(cacc[mt][nt][0] + bv.x, cacc[mt][nt][1] + bv.y);
            float2 r1 = make_float2(cacc[mt][nt][2] + bv.x, cacc[mt][nt][3] + bv.y);
            *(float2*)&base[(size_t)ni * 64] = r0;
            *(float2*)&base[(size_t)(ni + 8) * 64] = r1;
        }
    }
}

// ---------------------------------------------------------------------------
// Kernel: LayerNorm q,k -> bf16 hi/lo
// ---------------------------------------------------------------------------
__global__ void ln_qk_kernel(const float* __restrict__ qn_w, const float* __restrict__ qn_b,
                             const float* __restrict__ kn_w, const float* __restrict__ kn_b)
{
    const int ROWS = BHD * NN;
    int gid = blockIdx.x * 8 + (threadIdx.x >> 5);
    int lane = threadIdx.x & 31;
    if (gid >= 2 * ROWS) return;
    bool isq = gid < ROWS;
    int r = isq ? gid : gid - ROWS;
    const float* buf = isq ? g_q : g_k;
    __nv_bfloat16* oh = isq ? g_qh : g_kh;
    __nv_bfloat16* ol = isq ? g_ql : g_kl;
    const float* w = isq ? qn_w : kn_w;
    const float* bb = isq ? qn_b : kn_b;

    float x0 = buf[(size_t)r * 64 + lane];
    float x1 = buf[(size_t)r * 64 + 32 + lane];
    float s = x0 + x1;
#pragma unroll
    for (int off = 16; off >= 1; off >>= 1) s += __shfl_xor_sync(0xffffffffu, s, off);
    float mu = s * (1.0f / 64.0f);
    float d0 = x0 - mu, d1 = x1 - mu;
    float v = d0 * d0 + d1 * d1;
#pragma unroll
    for (int off = 16; off >= 1; off >>= 1) v += __shfl_xor_sync(0xffffffffu, v, off);
    float inv = rsqrtf(v * (1.0f / 64.0f) + 1e-5f);
    float y0 = d0 * inv * w[lane] + bb[lane];
    float y1 = d1 * inv * w[lane + 32] + bb[lane + 32];
    __nv_bfloat16 h0 = __float2bfloat16(y0);
    __nv_bfloat16 h1 = __float2bfloat16(y1);
    oh[(size_t)r * 64 + lane]      = h0;
    oh[(size_t)r * 64 + 32 + lane] = h1;
    ol[(size_t)r * 64 + lane]      = __float2bfloat16(y0 - __bfloat162float(h0));
    ol[(size_t)r * 64 + 32 + lane] = __float2bfloat16(y1 - __bfloat162float(h1));
}

// ---------------------------------------------------------------------------
// Kernel: v [bh][n][64] fp32 -> vt [bh][d][n] bf16 hi/lo
// ---------------------------------------------------------------------------
__global__ void vt_kernel()
{
    __shared__ float ts[64][65];
    int bh = blockIdx.y;
    int n0 = blockIdx.x * 64;
    int tid = threadIdx.x;
    const float* vb = g_v + (size_t)bh * NN * DD + (size_t)n0 * 64;

#pragma unroll
    for (int i = 0; i < 4; i++) {
        int f4 = tid + 256 * i;
        int r = f4 >> 4, c4 = (f4 & 15) * 4;
        float4 v = *(const float4*)(vb + (size_t)r * 64 + c4);
        ts[r][c4 + 0] = v.x; ts[r][c4 + 1] = v.y;
        ts[r][c4 + 2] = v.z; ts[r][c4 + 3] = v.w;
    }
    __syncthreads();

    int d = tid >> 2, ns = (tid & 3) * 16;
    __nv_bfloat16* oh = g_vth + (size_t)bh * DD * NN + (size_t)d * NN + n0 + ns;
    __nv_bfloat16* ol = g_vtl + (size_t)bh * DD * NN + (size_t)d * NN + n0 + ns;
#pragma unroll
    for (int j = 0; j < 8; j++) {
        float a = ts[ns + 2 * j][d], b = ts[ns + 2 * j + 1][d];
        *(u32*)&oh[2 * j] = pack_hi2(a, b);
        *(u32*)&ol[2 * j] = pack_lo2(a, b);
    }
}

// ---------------------------------------------------------------------------
// Kernel: flash attention (precomputed fp16 bias, ex2.approx softmax)
// ---------------------------------------------------------------------------
#define QS GP
#define SM_QHI   0
#define SM_QLO   (SM_QHI  + 128*QS*2)
#define SM_KHI   (SM_QLO  + 128*QS*2)
#define SM_KLO   (SM_KHI  + 64*QS*2)
#define SM_VTHI  (SM_KLO  + 64*QS*2)
#define SM_VTLO  (SM_VTHI + 64*QS*2)
#define ATTN_SMEM_BYTES (SM_VTLO + 64*QS*2)

__global__ __launch_bounds__(256, 2) void attn_kernel()
{
    extern __shared__ char smc[];
    __nv_bfloat16* Qhi  = (__nv_bfloat16*)(smc + SM_QHI);
    __nv_bfloat16* Qlo  = (__nv_bfloat16*)(smc + SM_QLO);
    __nv_bfloat16* Khi  = (__nv_bfloat16*)(smc + SM_KHI);
    __nv_bfloat16* Klo  = (__nv_bfloat16*)(smc + SM_KLO);
    __nv_bfloat16* Vthi = (__nv_bfloat16*)(smc + SM_VTHI);
    __nv_bfloat16* Vtlo = (__nv_bfloat16*)(smc + SM_VTLO);

    const int tid = threadIdx.x;
    const int w = tid >> 5, lane = tid & 31;
    const int qr = lane >> 2, qc = lane & 3;
    const int q0 = blockIdx.x * 128;
    const int bh = blockIdx.y;
    const int bi = bh >> 3, head = bh & 7;

    const u32 sQhi = smem_u32(Qhi), sQlo = smem_u32(Qlo);
    const u32 sKhi = smem_u32(Khi), sKlo = smem_u32(Klo);
    const u32 sVhi = smem_u32(Vthi), sVlo = smem_u32(Vtlo);
    const u32 aoff = lane_a_off(lane), boff = lane_b_off(lane);

    const __nv_bfloat16* qbh = g_qh + (size_t)bh * NN * DD + (size_t)q0 * 64;
    const __nv_bfloat16* qbl = g_ql + (size_t)bh * NN * DD + (size_t)q0 * 64;
    const __nv_bfloat16* kbh = g_kh + (size_t)bh * NN * DD;
    const __nv_bfloat16* kbl = g_kl + (size_t)bh * NN * DD;
    const __nv_bfloat16* vbh = g_vth + (size_t)bh * DD * NN;
    const __nv_bfloat16* vbl = g_vtl + (size_t)bh * DD * NN;

#pragma unroll
    for (int s = 0; s < 4; s++) {
        int idx = tid + 256 * s;
        int r = idx >> 3, seg = (idx & 7) * 8;
        *(uint4*)&Qhi[r * QS + seg] = *(const uint4*)&qbh[(size_t)r * 64 + seg];
        *(uint4*)&Qlo[r * QS + seg] = *(const uint4*)&qbl[(size_t)r * 64 + seg];
    }

    const int lrow0 = w * 16 + qr;
    const __half* eb0 = g_eb + (size_t)(q0 + lrow0) * NN;
    const __half* eb1 = g_eb + (size_t)(q0 + lrow0 + 8) * NN;

    float oacc[8][4];
#pragma unroll
    for (int i = 0; i < 8; i++)
#pragma unroll
        for (int j = 0; j < 4; j++) oacc[i][j] = 0.f;
    float lsum0 = 0.f, lsum1 = 0.f;
    float sacc[8][4];

    for (int kt = 0; kt < 32; kt++) {
        const int k0 = kt * 64;
        __syncthreads();
#pragma unroll
        for (int s = 0; s < 2; s++) {
            int idx = tid + 256 * s;
            int r = idx >> 3, seg = (idx & 7) * 8;
            *(uint4*)&Khi[r * QS + seg]  = *(const uint4*)&kbh[(size_t)(k0 + r) * 64 + seg];
            *(uint4*)&Klo[r * QS + seg]  = *(const uint4*)&kbl[(size_t)(k0 + r) * 64 + seg];
            *(uint4*)&Vthi[r * QS + seg] = *(const uint4*)&vbh[(size_t)r * NN + k0 + seg];
            *(uint4*)&Vtlo[r * QS + seg] = *(const uint4*)&vbl[(size_t)r * NN + k0 + seg];
        }
        __syncthreads();

        // ---- S = Q K^T ----
#pragma unroll
        for (int i = 0; i < 8; i++)
#pragma unroll
            for (int j = 0; j < 4; j++) sacc[i][j] = 0.f;

#pragma unroll
        for (int ks = 0; ks < 4; ks++) {
            const u32 kbyte = ks * 32;
            u32 ra = (u32)(w * 16 * QS * 2) + kbyte + aoff;
            u32 qh0, qh1, qh2, qh3, ql0, ql1, ql2, ql3;
            ldsm4(qh0, qh1, qh2, qh3, sQhi + ra);
            ldsm4(ql0, ql1, ql2, ql3, sQlo + ra);
#pragma unroll
            for (int np = 0; np < 4; np++) {
                u32 rb = (u32)(np * 16 * QS * 2) + kbyte + boff;
                u32 kh0a, kh1a, kh0b, kh1b, kl0a, kl1a, kl0b, kl1b;
                ldsm4(kh0a, kh1a, kh0b, kh1b, sKhi + rb);
                ldsm4(kl0a, kl1a, kl0b, kl1b, sKlo + rb);
                mma16816(sacc[2*np],   qh0, qh1, qh2, qh3, kh0a, kh1a);
                mma16816(sacc[2*np],   qh0, qh1, qh2, qh3, kl0a, kl1a);
                mma16816(sacc[2*np],   ql0, ql1, ql2, ql3, kh0a, kh1a);
                mma16816(sacc[2*np+1], qh0, qh1, qh2, qh3, kh0b, kh1b);
                mma16816(sacc[2*np+1], qh0, qh1, qh2, qh3, kl0b, kl1b);
                mma16816(sacc[2*np+1], ql0, ql1, ql2, ql3, kh0b, kh1b);
            }
        }

        // ---- softmax (fixed max 8, precomputed fp16 bias) ----
#pragma unroll
        for (int nt = 0; nt < 8; nt++) {
            int cb = nt * 8 + 2 * qc;
            float2 e0 = __half22float2(*(const __half2*)&eb0[k0 + cb]);
            float2 e1 = __half22float2(*(const __half2*)&eb1[k0 + cb]);
            float p0 = ex2f(fmaf(e0.x, -1.44269504f,
                            fmaf(sacc[nt][0], 0.18033688f, -11.54156036f)));
            float p1 = ex2f(fmaf(e0.y, -1.44269504f,
                            fmaf(sacc[nt][1], 0.18033688f, -11.54156036f)));
            float p2 = ex2f(fmaf(e1.x, -1.44269504f,
                            fmaf(sacc[nt][2], 0.18033688f, -11.54156036f)));
            float p3 = ex2f(fmaf(e1.y, -1.44269504f,
                            fmaf(sacc[nt][3], 0.18033688f, -11.54156036f)));
            lsum0 += p0 + p1;
            lsum1 += p2 + p3;
            sacc[nt][0] = p0; sacc[nt][1] = p1; sacc[nt][2] = p2; sacc[nt][3] = p3;
        }

        // ---- O += P V ----
#pragma unroll
        for (int ks = 0; ks < 4; ks++) {
            const u32 kbyte = ks * 32;
            u32 ah0 = pack_hi2(sacc[2 * ks][0],     sacc[2 * ks][1]);
            u32 ah1 = pack_hi2(sacc[2 * ks][2],     sacc[2 * ks][3]);
            u32 ah2 = pack_hi2(sacc[2 * ks + 1][0], sacc[2 * ks + 1][1]);
            u32 ah3 = pack_hi2(sacc[2 * ks + 1][2], sacc[2 * ks + 1][3]);
            u32 al0 = pack_lo2(sacc[2 * ks][0],     sacc[2 * ks][1]);
            u32 al1 = pack_lo2(sacc[2 * ks][2],     sacc[2 * ks][3]);
            u32 al2 = pack_lo2(sacc[2 * ks + 1][0], sacc[2 * ks + 1][1]);
            u32 al3 = pack_lo2(sacc[2 * ks + 1][2], sacc[2 * ks + 1][3]);
#pragma unroll
            for (int np = 0; np < 4; np++) {
                u32 rb = (u32)(np * 16 * QS * 2) + kbyte + boff;
                u32 vh0a, vh1a, vh0b, vh1b, vl0a, vl1a, vl0b, vl1b;
                ldsm4(vh0a, vh1a, vh0b, vh1b, sVhi + rb);
                ldsm4(vl0a, vl1a, vl0b, vl1b, sVlo + rb);
                mma16816(oacc[2*np],   ah0, ah1, ah2, ah3, vh0a, vh1a);
                mma16816(oacc[2*np],   ah0, ah1, ah2, ah3, vl0a, vl1a);
                mma16816(oacc[2*np],   al0, al1, al2, al3, vh0a, vh1a);
                mma16816(oacc[2*np+1], ah0, ah1, ah2, ah3, vh0b, vh1b);
                mma16816(oacc[2*np+1], ah0, ah1, ah2, ah3, vl0b, vl1b);
                mma16816(oacc[2*np+1], al0, al1, al2, al3, vh0b, vh1b);
            }
        }
    }

#pragma unroll
    for (int off = 1; off <= 2; off <<= 1) {
        lsum0 += __shfl_xor_sync(0xffffffffu, lsum0, off);
        lsum1 += __shfl_xor_sync(0xffffffffu, lsum1, off);
    }
    float inv0 = 1.0f / lsum0, inv1 = 1.0f / lsum1;

    __nv_bfloat16* obh = g_atth + ((size_t)bi * NN + q0) * DIM + head * 64;
    __nv_bfloat16* obl = g_attl + ((size_t)bi * NN + q0) * DIM + head * 64;
#pragma unroll
    for (int nt = 0; nt < 8; nt++) {
        int cb = nt * 8 + 2 * qc;
        float a0 = oacc[nt][0] * inv0, a1 = oacc[nt][1] * inv0;
        float b0 = oacc[nt][2] * inv1, b1 = oacc[nt][3] * inv1;
        *(u32*)&obh[(size_t)lrow0 * DIM + cb]       = pack_hi2(a0, a1);
        *(u32*)&obl[(size_t)lrow0 * DIM + cb]       = pack_lo2(a0, a1);
        *(u32*)&obh[(size_t)(lrow0 + 8) * DIM + cb] = pack_hi2(b0, b1);
        *(u32*)&obl[(size_t)(lrow0 + 8) * DIM + cb] = pack_lo2(b0, b1);
    }
}

// ---------------------------------------------------------------------------
// Kernel: output GEMM — 64-row tiles, grid (4, 64) = 256 CTAs
// ---------------------------------------------------------------------------
__global__ __launch_bounds__(256, 2) void out_gemm_kernel(
    const float* __restrict__ bout, float* __restrict__ out)
{
    extern __shared__ char smc[];
    const int row0 = blockIdx.y * 64;
    const int col0 = blockIdx.x * 128;
    const int lane = threadIdx.x & 31;
    const int w = threadIdx.x >> 5;
    const int qr = lane >> 2, qc = lane & 3;
    const int wm = w >> 2, wn = w & 3;

    float cacc[2][4][4];
    gemm_mma_body_bf16<2>(g_atth + (size_t)row0 * 512, g_attl + (size_t)row0 * 512,
                          g_wouth + (size_t)col0 * 512, g_woutl + (size_t)col0 * 512,
                          smc, cacc);

#pragma unroll
    for (int mt = 0; mt < 2; mt++) {
        int grow = row0 + wm * 32 + mt * 16 + qr;
#pragma unroll
        for (int nt = 0; nt < 4; nt++) {
            int c0 = col0 + wn * 32 + nt * 8 + 2 * qc;
            float2 bv = *(const float2*)(bout + c0);
            float2 r0 = make_float2(cacc[mt][nt][0] + bv.x, cacc[mt][nt][1] + bv.y);
            float2 r1 = make_float2(cacc[mt][nt][2] + bv.x, cacc[mt][nt][3] + bv.y);
            *(float2*)&out[(size_t)grow * 512 + c0] = r0;
            *(float2*)&out[(size_t)(grow + 8) * 512 + c0] = r1;
        }
    }
}

// ---------------------------------------------------------------------------
extern "C" void kernel_launch(void* const* d_in, const int* in_sizes, int n_in,
                              void* d_out, int out_size)
{
    const float* x    = (const float*)d_in[0];
    const float* pos  = (const float*)d_in[1];
    const float* W_in = (const float*)d_in[2];
    const float* b_in = (const float*)d_in[3];
    const float* qn_w = (const float*)d_in[4];
    const float* qn_b = (const float*)d_in[5];
    const float* kn_w = (const float*)d_in[6];
    const float* kn_b = (const float*)d_in[7];
    const float* W_out= (const float*)d_in[8];
    const float* b_out= (const float*)d_in[9];
    float* out = (float*)d_out;

    cudaFuncSetAttribute(qkv_gemm_kernel, cudaFuncAttributeMaxDynamicSharedMemorySize, GEMM_SMEM_BYTES);
    cudaFuncSetAttribute(out_gemm_kernel, cudaFuncAttributeMaxDynamicSharedMemorySize, GEMM_SMEM_BYTES);
    cudaFuncSetAttribute(attn_kernel, cudaFuncAttributeMaxDynamicSharedMemorySize, ATTN_SMEM_BYTES);

    __nv_bfloat16 *winh, *winl, *wouth, *woutl;
    cudaGetSymbolAddress((void**)&winh, g_winh);
    cudaGetSymbolAddress((void**)&winl, g_winl);
    cudaGetSymbolAddress((void**)&wouth, g_wouth);
    cudaGetSymbolAddress((void**)&woutl, g_woutl);

    prep_x_kernel<<<BN * DIM / 4 / 256, 256>>>(x);
    prep_wt_kernel<<<dim3(1536 / 32, 512 / 32), dim3(32, 8)>>>(W_in, winh, winl, 1536);
    prep_wt_kernel<<<dim3(512 / 32, 512 / 32), dim3(32, 8)>>>(W_out, wouth, woutl, 512);
    bias_kernel<<<NN / 16, 256>>>(pos);

    qkv_gemm_kernel<<<dim3(12, 32), 256, GEMM_SMEM_BYTES>>>(b_in);
    ln_qk_kernel<<<(2 * BHD * NN) / 8, 256>>>(qn_w, qn_b, kn_w, kn_b);
    vt_kernel<<<dim3(NN / 64, BHD), 256>>>();
    attn_kernel<<<dim3(16, 16), 256, ATTN_SMEM_BYTES>>>();
    out_gemm_kernel<<<dim3(4, 64), 256, GEMM_SMEM_BYTES>>>(b_out, out);
}